// round 6
// baseline (speedup 1.0000x reference)
#include <cuda_runtime.h>
#include <cuda_bf16.h>
#include <math.h>

#define NPTS 16384
#define KNN  16
#define G    16
#define GC   (G * G * G)     // 4096 cells, ~4 pts/cell
#define HCELL (1.0f / G)

// ---------------- scratch (device globals, no allocations) ----------------
__device__ float4 d_pts4[NPTS];
__device__ float  d_ptsPad[NPTS * 16];
__device__ float  d_imfT[NPTS * 32];
__device__ float  d_T1[16 * 64];
__device__ float  d_T2[64 * 128];
__device__ float  d_T3[32 * 64];
__device__ float  d_T4[64 * 128];
__device__ float  d_T5[128 * 256];
__device__ float  d_T6[256 * 128];
__device__ float  d_T7[416 * 32];
__device__ float  d_t1[NPTS * 64];
__device__ float  d_cf[NPTS * 128];
__device__ float  d_t2[NPTS * 64];
__device__ float  d_g [NPTS * 128];
__device__ float  d_h1[NPTS * 256];
__device__ float  d_h [NPTS * 128];
__device__ int    d_knn[NPTS * KNN];
// grid structures: [0:GC) = counts, [GC:2GC) = scatter cursors (zeroed in prep)
__device__ int    d_cellCnt[2 * GC];
__device__ int    d_cellStart[GC + 1];
__device__ int    d_ptCell[NPTS];
__device__ float4 d_spts[NPTS];
__device__ int    d_sidx[NPTS];

__device__ __forceinline__ float lrelu(float x) { return x > 0.f ? x : 0.01f * x; }

// ---------------- prep (also zeroes grid counters; runs before hist) ----------------
__global__ void prep_kernel(const float* __restrict__ img, const float* __restrict__ cloud,
                            const float* __restrict__ c1w, const float* __restrict__ c2w,
                            const float* __restrict__ ps1w, const float* __restrict__ ps2w,
                            const float* __restrict__ pc1w, const float* __restrict__ pc2w,
                            const float* __restrict__ finw)
{
    const int stride = gridDim.x * blockDim.x;
    const int i0 = blockIdx.x * blockDim.x + threadIdx.x;
    for (int t = i0; t < 2 * GC; t += stride) d_cellCnt[t] = 0;
    for (int n = i0; n < NPTS; n += stride) {
        float x = cloud[n * 3 + 0], y = cloud[n * 3 + 1], z = cloud[n * 3 + 2];
        d_pts4[n] = make_float4(x, y, z, x * x + y * y + z * z);
        float* row = &d_ptsPad[n * 16];
        row[0] = x; row[1] = y; row[2] = z;
        #pragma unroll
        for (int k = 3; k < 16; k++) row[k] = 0.f;
    }
    for (int t = i0; t < NPTS * 32; t += stride)
        d_imfT[t] = img[(t & 31) * NPTS + (t >> 5)];
    for (int t = i0; t < 16 * 64; t += stride) {
        int k = t >> 6, j = t & 63;
        d_T1[t] = (k < 3) ? pc1w[j * 3 + k] : 0.f;
    }
    for (int t = i0; t < 64 * 128; t += stride) { int k = t >> 7, c = t & 127; d_T2[t] = pc2w[c * 64 + k]; }
    for (int t = i0; t < 32 * 64;  t += stride) { int k = t >> 6, j = t & 63;  d_T3[t] = c1w[j * 32 + k]; }
    for (int t = i0; t < 64 * 128; t += stride) { int k = t >> 7, c = t & 127; d_T4[t] = c2w[c * 64 + k]; }
    for (int t = i0; t < 128 * 256; t += stride) { int k = t >> 8, c = t & 255; d_T5[t] = ps1w[c * 128 + k]; }
    for (int t = i0; t < 256 * 128; t += stride) { int k = t >> 7, c = t & 127; d_T6[t] = ps2w[c * 256 + k]; }
    for (int t = i0; t < 416 * 32;  t += stride) { int c = t >> 5, j = t & 31;  d_T7[t] = finw[j * 416 + c]; }
}

// ---------------- grid build ----------------
__global__ void hist_kernel(const float* __restrict__ cloud)
{
    const int n = blockIdx.x * blockDim.x + threadIdx.x;
    if (n >= NPTS) return;
    float x = cloud[n * 3 + 0], y = cloud[n * 3 + 1], z = cloud[n * 3 + 2];
    int cx = min(G - 1, max(0, (int)(x * G)));
    int cy = min(G - 1, max(0, (int)(y * G)));
    int cz = min(G - 1, max(0, (int)(z * G)));
    int c = (cz * G + cy) * G + cx;
    d_ptCell[n] = c;
    atomicAdd(&d_cellCnt[c], 1);
}

__global__ void scan_kernel()   // one block, 1024 threads, 4096 cells
{
    __shared__ int ssum[1024];
    const int t = threadIdx.x;
    int c0 = d_cellCnt[4 * t + 0], c1 = d_cellCnt[4 * t + 1];
    int c2 = d_cellCnt[4 * t + 2], c3 = d_cellCnt[4 * t + 3];
    int s = c0 + c1 + c2 + c3;
    ssum[t] = s;
    __syncthreads();
    for (int off = 1; off < 1024; off <<= 1) {
        int v = (t >= off) ? ssum[t - off] : 0;
        __syncthreads();
        ssum[t] += v;
        __syncthreads();
    }
    int excl = ssum[t] - s;
    d_cellStart[4 * t + 0] = excl;
    d_cellStart[4 * t + 1] = excl + c0;
    d_cellStart[4 * t + 2] = excl + c0 + c1;
    d_cellStart[4 * t + 3] = excl + c0 + c1 + c2;
    if (t == 1023) d_cellStart[GC] = ssum[1023];
}

__global__ void scatter_kernel()
{
    const int n = blockIdx.x * blockDim.x + threadIdx.x;
    if (n >= NPTS) return;
    const int c = d_ptCell[n];
    const int pos = d_cellStart[c] + atomicAdd(&d_cellCnt[GC + c], 1);
    d_spts[pos] = d_pts4[n];
    d_sidx[pos] = n;
}

// ---------------- KNN helpers ----------------
__device__ __forceinline__ void insert16(float (&kd)[KNN], int (&ki)[KNN], float d, int idx)
{
    kd[KNN - 1] = d; ki[KNN - 1] = idx;
    #pragma unroll
    for (int t = KNN - 1; t > 0; --t) {
        if (kd[t] < kd[t - 1]) {
            float td = kd[t]; kd[t] = kd[t - 1]; kd[t - 1] = td;
            int   ti = ki[t]; ki[t] = ki[t - 1]; ki[t - 1] = ti;
        }
    }
}

__device__ __forceinline__ void scan_cell(int cell, float qx, float qy, float qz,
                                          float (&kd)[KNN], int (&ki)[KNN])
{
    const int st = d_cellStart[cell], en = d_cellStart[cell + 1];
    int p = st;
    for (; p + 1 < en; p += 2) {
        const float4 a = d_spts[p];
        const float4 b = d_spts[p + 1];
        const float dax = qx - a.x, day = qy - a.y, daz = qz - a.z;
        const float dbx = qx - b.x, dby = qy - b.y, dbz = qz - b.z;
        const float da = fmaf(dax, dax, fmaf(day, day, daz * daz));
        const float db = fmaf(dbx, dbx, fmaf(dby, dby, dbz * dbz));
        if (da < kd[KNN - 1]) insert16(kd, ki, da, p);
        if (db < kd[KNN - 1]) insert16(kd, ki, db, p + 1);
    }
    if (p < en) {
        const float4 a = d_spts[p];
        const float dax = qx - a.x, day = qy - a.y, daz = qz - a.z;
        const float da = fmaf(dax, dax, fmaf(day, day, daz * daz));
        if (da < kd[KNN - 1]) insert16(kd, ki, da, p);
    }
}

// ---------------- KNN via grid: 2 threads per (sorted) query ----------------
// Pair threads scan alternating cells of the same shell enumeration, keep private
// sorted top-16, then merge exactly via smem. Stop when min(a15,b15) < (m*h)^2
// (upper bound on merged 16th-NN distance), warp-uniform to keep shfl converged.
__global__ void __launch_bounds__(256) knn_grid_kernel()
{
    __shared__ float sd[256][17];
    __shared__ int   si[256][17];
    const int tid = threadIdx.x;
    const int par = tid & 1;
    const int s = blockIdx.x * 128 + (tid >> 1);     // query = sorted position
    const float4 pq = d_spts[s];
    const int cx = min(G - 1, max(0, (int)(pq.x * G)));
    const int cy = min(G - 1, max(0, (int)(pq.y * G)));
    const int cz = min(G - 1, max(0, (int)(pq.z * G)));

    float kd[KNN]; int ki[KNN];
    #pragma unroll
    for (int t = 0; t < KNN; t++) { kd[t] = INFINITY; ki[t] = 0; }

    int cc = 0;   // cell counter: identical sequence for both pair threads
    for (int m = 0; m < G; m++) {
        const int x0 = max(cx - m, 0), x1 = min(cx + m, G - 1);
        const int y0 = max(cy - m, 0), y1 = min(cy + m, G - 1);
        const int z0 = max(cz - m, 0), z1 = min(cz + m, G - 1);
        for (int z = z0; z <= z1; z++) {
            const bool zs = (z == cz - m) || (z == cz + m);
            for (int y = y0; y <= y1; y++) {
                const bool edge = zs || (y == cy - m) || (y == cy + m);
                if (edge) {
                    const int rowc = (z * G + y) * G;
                    for (int x = x0; x <= x1; x++) {
                        if ((cc & 1) == par) scan_cell(rowc + x, pq.x, pq.y, pq.z, kd, ki);
                        cc++;
                    }
                } else {
                    if (cx - m >= 0) {
                        if ((cc & 1) == par) scan_cell((z * G + y) * G + cx - m, pq.x, pq.y, pq.z, kd, ki);
                        cc++;
                    }
                    if (cx + m <= G - 1) {
                        if ((cc & 1) == par) scan_cell((z * G + y) * G + cx + m, pq.x, pq.y, pq.z, kd, ki);
                        cc++;
                    }
                }
            }
        }
        const float bound = (float)m * HCELL;
        const float other = __shfl_xor_sync(0xffffffffu, kd[KNN - 1], 1);
        const bool done = fminf(kd[KNN - 1], other) < bound * bound;
        if (__all_sync(0xffffffffu, done)) break;
    }

    // stash partial sorted lists, pair-merge on even thread
    #pragma unroll
    for (int t = 0; t < KNN; t++) { sd[tid][t] = kd[t]; si[tid][t] = ki[t]; }
    __syncwarp();

    if (par == 0) {
        const int orig = d_sidx[s];
        int ia = 0, ib = 0;
        #pragma unroll 1
        for (int r = 0; r < KNN; r++) {
            const float va = sd[tid][ia], vb = sd[tid + 1][ib];
            int sel;
            if (va <= vb) { sel = si[tid][ia]; ia++; }
            else          { sel = si[tid + 1][ib]; ib++; }
            d_knn[orig * KNN + r] = d_sidx[sel];
        }
    }
}

// ---------------- generic fp32 GEMM: C = act(A[M,K] @ Bt[K,Nc] + bias) ----------------
__global__ void __launch_bounds__(256) gemm_kernel(const float* __restrict__ A,
                                                   const float* __restrict__ Bt,
                                                   const float* __restrict__ bias,
                                                   float* __restrict__ C,
                                                   int K, int Nc, int act)
{
    __shared__ float As[16][68];
    __shared__ float Bs[16][64];
    const int tid  = threadIdx.x;
    const int tcol = tid & 15, trow = tid >> 4;
    const int m0 = blockIdx.y * 64, n0 = blockIdx.x * 64;
    const int lmA = tid >> 2, lkA = (tid & 3) << 2;
    const int lkB = tid >> 4, lnB = (tid & 15) << 2;

    float acc[4][4];
    #pragma unroll
    for (int i = 0; i < 4; i++)
        #pragma unroll
        for (int j = 0; j < 4; j++) acc[i][j] = 0.f;

    for (int k0 = 0; k0 < K; k0 += 16) {
        float4 a = *(const float4*)&A[(m0 + lmA) * K + k0 + lkA];
        As[lkA + 0][lmA] = a.x; As[lkA + 1][lmA] = a.y;
        As[lkA + 2][lmA] = a.z; As[lkA + 3][lmA] = a.w;
        *(float4*)&Bs[lkB][lnB] = *(const float4*)&Bt[(k0 + lkB) * Nc + n0 + lnB];
        __syncthreads();
        #pragma unroll
        for (int k = 0; k < 16; k++) {
            float4 av = *(const float4*)&As[k][trow << 2];
            float4 bv = *(const float4*)&Bs[k][tcol << 2];
            float ar[4] = {av.x, av.y, av.z, av.w};
            float br[4] = {bv.x, bv.y, bv.z, bv.w};
            #pragma unroll
            for (int i = 0; i < 4; i++)
                #pragma unroll
                for (int j = 0; j < 4; j++)
                    acc[i][j] = fmaf(ar[i], br[j], acc[i][j]);
        }
        __syncthreads();
    }

    float4 bb = *(const float4*)&bias[n0 + (tcol << 2)];
    const float bbr[4] = {bb.x, bb.y, bb.z, bb.w};
    #pragma unroll
    for (int i = 0; i < 4; i++) {
        const int m = m0 + (trow << 2) + i;
        float4 r;
        float v0 = acc[i][0] + bbr[0], v1 = acc[i][1] + bbr[1];
        float v2 = acc[i][2] + bbr[2], v3 = acc[i][3] + bbr[3];
        if (act) { v0 = lrelu(v0); v1 = lrelu(v1); v2 = lrelu(v2); v3 = lrelu(v3); }
        r.x = v0; r.y = v1; r.z = v2; r.w = v3;
        *(float4*)&C[m * Nc + n0 + (tcol << 2)] = r;
    }
}

// ---------------- final: softmax weights, weighted max-pool, concat, GEMV ----------------
__global__ void __launch_bounds__(256) final_kernel(const float* __restrict__ img,
                                                    const float* __restrict__ fb,
                                                    float* __restrict__ out)
{
    __shared__ float swgt[8][KNN];
    __shared__ int   sidx[8][KNN];
    __shared__ float sfin[8][416];
    const int w = threadIdx.x >> 5, lane = threadIdx.x & 31;
    const int n = blockIdx.x * 8 + w;

    const float4 pq = d_pts4[n];
    float negd = -INFINITY; int myi = 0;
    if (lane < KNN) {
        myi = d_knn[n * KNN + lane];
        float4 pc = d_pts4[myi];
        float dx = pq.x - pc.x, dy = pq.y - pc.y, dz = pq.z - pc.z;
        negd = -sqrtf(fmaxf(dx * dx + dy * dy + dz * dz, 1e-12f));
    }
    float m = negd;
    #pragma unroll
    for (int s = 16; s > 0; s >>= 1) m = fmaxf(m, __shfl_xor_sync(0xffffffffu, m, s));
    float e = (lane < KNN) ? expf(negd - m) : 0.f;
    float ss = e;
    #pragma unroll
    for (int s = 16; s > 0; s >>= 1) ss += __shfl_xor_sync(0xffffffffu, ss, s);
    if (lane < KNN) { swgt[w][lane] = e / ss; sidx[w][lane] = myi; }
    __syncwarp();

    float4 sf = make_float4(-INFINITY, -INFINITY, -INFINITY, -INFINITY);
    float4 sp = make_float4(-INFINITY, -INFINITY, -INFINITY, -INFINITY);
    #pragma unroll
    for (int k = 0; k < KNN; k++) {
        const int ik = sidx[w][k];
        const float wk = swgt[w][k];
        const float4 gv = *(const float4*)&d_g[ik * 128 + (lane << 2)];
        const float4 hv = *(const float4*)&d_h[ik * 128 + (lane << 2)];
        sf.x = fmaxf(sf.x, gv.x * wk); sf.y = fmaxf(sf.y, gv.y * wk);
        sf.z = fmaxf(sf.z, gv.z * wk); sf.w = fmaxf(sf.w, gv.w * wk);
        sp.x = fmaxf(sp.x, hv.x * wk); sp.y = fmaxf(sp.y, hv.y * wk);
        sp.z = fmaxf(sp.z, hv.z * wk); sp.w = fmaxf(sp.w, hv.w * wk);
    }
    const int c4 = lane << 2;
    sfin[w][c4 + 0] = lrelu(sp.x); sfin[w][c4 + 1] = lrelu(sp.y);
    sfin[w][c4 + 2] = lrelu(sp.z); sfin[w][c4 + 3] = lrelu(sp.w);
    sfin[w][128 + lane] = lrelu(img[lane * NPTS + n]);
    sfin[w][160 + c4 + 0] = lrelu(sf.x); sfin[w][160 + c4 + 1] = lrelu(sf.y);
    sfin[w][160 + c4 + 2] = lrelu(sf.z); sfin[w][160 + c4 + 3] = lrelu(sf.w);
    const float4 cv = *(const float4*)&d_cf[n * 128 + c4];
    sfin[w][288 + c4 + 0] = lrelu(cv.x); sfin[w][288 + c4 + 1] = lrelu(cv.y);
    sfin[w][288 + c4 + 2] = lrelu(cv.z); sfin[w][288 + c4 + 3] = lrelu(cv.w);
    __syncwarp();

    float acc = fb[lane];
    #pragma unroll 8
    for (int c = 0; c < 416; c++)
        acc = fmaf(sfin[w][c], d_T7[c * 32 + lane], acc);
    out[lane * NPTS + n] = acc;
}

// ---------------- launch ----------------
extern "C" void kernel_launch(void* const* d_in, const int* in_sizes, int n_in,
                              void* d_out, int out_size)
{
    const float* img   = (const float*)d_in[0];
    const float* cloud = (const float*)d_in[1];
    const float* c1w  = (const float*)d_in[2];  const float* c1b  = (const float*)d_in[3];
    const float* c2w  = (const float*)d_in[4];  const float* c2b  = (const float*)d_in[5];
    const float* ps1w = (const float*)d_in[6];  const float* ps1b = (const float*)d_in[7];
    const float* ps2w = (const float*)d_in[8];  const float* ps2b = (const float*)d_in[9];
    const float* pc1w = (const float*)d_in[10]; const float* pc1b = (const float*)d_in[11];
    const float* pc2w = (const float*)d_in[12]; const float* pc2b = (const float*)d_in[13];
    const float* finw = (const float*)d_in[14]; const float* finb = (const float*)d_in[15];
    float* out = (float*)d_out;

    void *pPtsPad, *pT1, *pT2, *pT3, *pT4, *pT5, *pT6;
    void *pt1, *pcf, *pimfT, *pt2, *pg, *ph1, *ph;
    cudaGetSymbolAddress(&pPtsPad, d_ptsPad);
    cudaGetSymbolAddress(&pT1, d_T1); cudaGetSymbolAddress(&pT2, d_T2);
    cudaGetSymbolAddress(&pT3, d_T3); cudaGetSymbolAddress(&pT4, d_T4);
    cudaGetSymbolAddress(&pT5, d_T5); cudaGetSymbolAddress(&pT6, d_T6);
    cudaGetSymbolAddress(&pt1, d_t1); cudaGetSymbolAddress(&pcf, d_cf);
    cudaGetSymbolAddress(&pimfT, d_imfT); cudaGetSymbolAddress(&pt2, d_t2);
    cudaGetSymbolAddress(&pg, d_g); cudaGetSymbolAddress(&ph1, d_h1);
    cudaGetSymbolAddress(&ph, d_h);

    // launches 1-5 (no memsets anywhere): prep zeroes grid counters itself
    prep_kernel<<<256, 256>>>(img, cloud, c1w, c2w, ps1w, ps2w, pc1w, pc2w, finw);
    hist_kernel<<<NPTS / 256, 256>>>(cloud);
    scan_kernel<<<1, 1024>>>();
    scatter_kernel<<<NPTS / 256, 256>>>();
    gemm_kernel<<<dim3(1, NPTS / 64), 256>>>((const float*)pPtsPad, (const float*)pT1, pc1b, (float*)pt1, 16, 64, 1);
    // launch 6: knn (ncu -s 5 -c 1 capture target)
    knn_grid_kernel<<<NPTS * 2 / 256, 256>>>();

    gemm_kernel<<<dim3(2, NPTS / 64), 256>>>((const float*)pt1, (const float*)pT2, pc2b, (float*)pcf, 64, 128, 0);
    gemm_kernel<<<dim3(1, NPTS / 64), 256>>>((const float*)pimfT, (const float*)pT3, c1b, (float*)pt2, 32, 64, 1);
    gemm_kernel<<<dim3(2, NPTS / 64), 256>>>((const float*)pt2, (const float*)pT4, c2b, (float*)pg, 64, 128, 0);
    gemm_kernel<<<dim3(4, NPTS / 64), 256>>>((const float*)pcf, (const float*)pT5, ps1b, (float*)ph1, 128, 256, 1);
    gemm_kernel<<<dim3(2, NPTS / 64), 256>>>((const float*)ph1, (const float*)pT6, ps2b, (float*)ph, 256, 128, 0);

    final_kernel<<<NPTS / 8, 256>>>(img, finb, out);
}

// round 7
// speedup vs baseline: 1.4747x; 1.4747x over previous
#include <cuda_runtime.h>
#include <cuda_bf16.h>
#include <math.h>

#define NPTS 16384
#define KNN  16
#define G    12
#define GC   (G * G * G)     // 1728 cells, ~9.5 pts/cell
#define HCELL (1.0f / G)
#define FULLM 0xffffffffu

// ---------------- scratch (device globals, no allocations) ----------------
__device__ float4 d_pts4[NPTS];
__device__ float  d_ptsPad[NPTS * 16];
__device__ float  d_imfT[NPTS * 32];
__device__ float  d_T1[16 * 64];
__device__ float  d_T2[64 * 128];
__device__ float  d_T3[32 * 64];
__device__ float  d_T4[64 * 128];
__device__ float  d_T5[128 * 256];
__device__ float  d_T6[256 * 128];
__device__ float  d_T7[416 * 32];
__device__ float  d_t1[NPTS * 64];
__device__ float  d_cf[NPTS * 128];
__device__ float  d_t2[NPTS * 64];
__device__ float  d_g [NPTS * 128];
__device__ float  d_h1[NPTS * 256];
__device__ float  d_h [NPTS * 128];
__device__ int    d_knn[NPTS * KNN];
// grid structures: [0:GC) = counts, [GC:2GC) = scatter cursors (zeroed in prep)
__device__ int    d_cellCnt[2 * GC];
__device__ int    d_cellStart[GC + 1];
__device__ int    d_ptCell[NPTS];
__device__ float4 d_spts[NPTS];
__device__ int    d_sidx[NPTS];

__device__ __forceinline__ float lrelu(float x) { return x > 0.f ? x : 0.01f * x; }

// ---------------- prep (also zeroes grid counters; runs before hist) ----------------
__global__ void prep_kernel(const float* __restrict__ img, const float* __restrict__ cloud,
                            const float* __restrict__ c1w, const float* __restrict__ c2w,
                            const float* __restrict__ ps1w, const float* __restrict__ ps2w,
                            const float* __restrict__ pc1w, const float* __restrict__ pc2w,
                            const float* __restrict__ finw)
{
    const int stride = gridDim.x * blockDim.x;
    const int i0 = blockIdx.x * blockDim.x + threadIdx.x;
    for (int t = i0; t < 2 * GC; t += stride) d_cellCnt[t] = 0;
    for (int n = i0; n < NPTS; n += stride) {
        float x = cloud[n * 3 + 0], y = cloud[n * 3 + 1], z = cloud[n * 3 + 2];
        d_pts4[n] = make_float4(x, y, z, x * x + y * y + z * z);
        float* row = &d_ptsPad[n * 16];
        row[0] = x; row[1] = y; row[2] = z;
        #pragma unroll
        for (int k = 3; k < 16; k++) row[k] = 0.f;
    }
    for (int t = i0; t < NPTS * 32; t += stride)
        d_imfT[t] = img[(t & 31) * NPTS + (t >> 5)];
    for (int t = i0; t < 16 * 64; t += stride) {
        int k = t >> 6, j = t & 63;
        d_T1[t] = (k < 3) ? pc1w[j * 3 + k] : 0.f;
    }
    for (int t = i0; t < 64 * 128; t += stride) { int k = t >> 7, c = t & 127; d_T2[t] = pc2w[c * 64 + k]; }
    for (int t = i0; t < 32 * 64;  t += stride) { int k = t >> 6, j = t & 63;  d_T3[t] = c1w[j * 32 + k]; }
    for (int t = i0; t < 64 * 128; t += stride) { int k = t >> 7, c = t & 127; d_T4[t] = c2w[c * 64 + k]; }
    for (int t = i0; t < 128 * 256; t += stride) { int k = t >> 8, c = t & 255; d_T5[t] = ps1w[c * 128 + k]; }
    for (int t = i0; t < 256 * 128; t += stride) { int k = t >> 7, c = t & 127; d_T6[t] = ps2w[c * 256 + k]; }
    for (int t = i0; t < 416 * 32;  t += stride) { int c = t >> 5, j = t & 31;  d_T7[t] = finw[j * 416 + c]; }
}

// ---------------- grid build ----------------
__global__ void hist_kernel(const float* __restrict__ cloud)
{
    const int n = blockIdx.x * blockDim.x + threadIdx.x;
    if (n >= NPTS) return;
    float x = cloud[n * 3 + 0], y = cloud[n * 3 + 1], z = cloud[n * 3 + 2];
    int cx = min(G - 1, max(0, (int)(x * G)));
    int cy = min(G - 1, max(0, (int)(y * G)));
    int cz = min(G - 1, max(0, (int)(z * G)));
    int c = (cz * G + cy) * G + cx;
    d_ptCell[n] = c;
    atomicAdd(&d_cellCnt[c], 1);
}

__global__ void scan_kernel()   // one block, 512 threads, 1728 cells
{
    __shared__ int ssum[512];
    const int t = threadIdx.x;
    int c0 = 0, c1 = 0, c2 = 0, c3 = 0;
    if (4 * t < GC) {
        c0 = d_cellCnt[4 * t + 0]; c1 = d_cellCnt[4 * t + 1];
        c2 = d_cellCnt[4 * t + 2]; c3 = d_cellCnt[4 * t + 3];
    }
    int s = c0 + c1 + c2 + c3;
    ssum[t] = s;
    __syncthreads();
    for (int off = 1; off < 512; off <<= 1) {
        int v = (t >= off) ? ssum[t - off] : 0;
        __syncthreads();
        ssum[t] += v;
        __syncthreads();
    }
    int excl = ssum[t] - s;
    if (4 * t < GC) {
        d_cellStart[4 * t + 0] = excl;
        d_cellStart[4 * t + 1] = excl + c0;
        d_cellStart[4 * t + 2] = excl + c0 + c1;
        d_cellStart[4 * t + 3] = excl + c0 + c1 + c2;
    }
    if (t == 511) d_cellStart[GC] = ssum[511];
}

__global__ void scatter_kernel()
{
    const int n = blockIdx.x * blockDim.x + threadIdx.x;
    if (n >= NPTS) return;
    const int c = d_ptCell[n];
    const int pos = d_cellStart[c] + atomicAdd(&d_cellCnt[GC + c], 1);
    d_spts[pos] = d_pts4[n];
    d_sidx[pos] = n;
}

// ---------------- KNN: one WARP per query, distributed top-16 ----------------
// Lanes 0..15 hold the current sorted top-16 (e ascending by lane). All control
// flow is warp-uniform: shells/rows are identical for all lanes; inserts are
// warp-parallel shifted-inserts driven by a uniform ballot mask.
__device__ __forceinline__ void warp_scan_range(int st, int en, int lane,
                                                float qx, float qy, float qz,
                                                float& e, int& ei, float& thresh)
{
    const int nb = (en - st + 31) >> 5;
    for (int b = 0; b < nb; b++) {
        const int p = st + (b << 5) + lane;
        float dcand = INFINITY;
        if (p < en) {
            const float4 c = d_spts[p];
            const float dx = qx - c.x, dy = qy - c.y, dz = qz - c.z;
            dcand = fmaf(dx, dx, fmaf(dy, dy, dz * dz));
        }
        unsigned mask = __ballot_sync(FULLM, dcand < thresh);
        while (mask) {
            const int src = __ffs(mask) - 1;
            mask &= mask - 1;
            const float v = __shfl_sync(FULLM, dcand, src);
            const int  vi = __shfl_sync(FULLM, p,     src);
            if (v < thresh) {               // uniform (v, thresh uniform)
                const unsigned le = __ballot_sync(FULLM, e <= v) & 0xFFFFu;
                const int pos = __popc(le); // insertion position
                const float pe = __shfl_up_sync(FULLM, e, 1);
                const int  pei = __shfl_up_sync(FULLM, ei, 1);
                if (lane > pos) { e = pe; ei = pei; }
                if (lane == pos) { e = v; ei = vi; }
                thresh = __shfl_sync(FULLM, e, 15);
            }
        }
    }
}

__global__ void __launch_bounds__(256) knn_warp_kernel()
{
    const int lane = threadIdx.x & 31;
    const int s = (blockIdx.x * 256 + threadIdx.x) >> 5;   // query = sorted position
    const float4 pq = d_spts[s];
    const int cx = min(G - 1, max(0, (int)(pq.x * G)));
    const int cy = min(G - 1, max(0, (int)(pq.y * G)));
    const int cz = min(G - 1, max(0, (int)(pq.z * G)));

    float e = INFINITY; int ei = 0;     // lane l<16: l-th smallest so far
    float thresh = INFINITY;

    for (int m = 0; m < G; m++) {
        const int x0 = max(cx - m, 0), x1 = min(cx + m, G - 1);
        const int y0 = max(cy - m, 0), y1 = min(cy + m, G - 1);
        const int z0 = max(cz - m, 0), z1 = min(cz + m, G - 1);
        for (int z = z0; z <= z1; z++) {
            const bool zs = (z == cz - m) || (z == cz + m);
            for (int y = y0; y <= y1; y++) {
                const bool edge = zs || (y == cy - m) || (y == cy + m);
                const int rowc = (z * G + y) * G;
                if (edge) {
                    // whole row of cells is one contiguous point range
                    warp_scan_range(d_cellStart[rowc + x0], d_cellStart[rowc + x1 + 1],
                                    lane, pq.x, pq.y, pq.z, e, ei, thresh);
                } else {
                    if (cx - m >= 0)
                        warp_scan_range(d_cellStart[rowc + cx - m], d_cellStart[rowc + cx - m + 1],
                                        lane, pq.x, pq.y, pq.z, e, ei, thresh);
                    if (cx + m <= G - 1)
                        warp_scan_range(d_cellStart[rowc + cx + m], d_cellStart[rowc + cx + m + 1],
                                        lane, pq.x, pq.y, pq.z, e, ei, thresh);
                }
            }
        }
        const float bound = (float)m * HCELL;
        if (thresh < bound * bound) break;   // uniform: all unvisited pts are >= m*h away
    }

    if (lane < KNN) {
        const int orig = d_sidx[s];
        d_knn[orig * KNN + lane] = d_sidx[ei];
    }
}

// ---------------- generic fp32 GEMM: C = act(A[M,K] @ Bt[K,Nc] + bias) ----------------
__global__ void __launch_bounds__(256) gemm_kernel(const float* __restrict__ A,
                                                   const float* __restrict__ Bt,
                                                   const float* __restrict__ bias,
                                                   float* __restrict__ C,
                                                   int K, int Nc, int act)
{
    __shared__ float As[16][68];
    __shared__ float Bs[16][64];
    const int tid  = threadIdx.x;
    const int tcol = tid & 15, trow = tid >> 4;
    const int m0 = blockIdx.y * 64, n0 = blockIdx.x * 64;
    const int lmA = tid >> 2, lkA = (tid & 3) << 2;
    const int lkB = tid >> 4, lnB = (tid & 15) << 2;

    float acc[4][4];
    #pragma unroll
    for (int i = 0; i < 4; i++)
        #pragma unroll
        for (int j = 0; j < 4; j++) acc[i][j] = 0.f;

    for (int k0 = 0; k0 < K; k0 += 16) {
        float4 a = *(const float4*)&A[(m0 + lmA) * K + k0 + lkA];
        As[lkA + 0][lmA] = a.x; As[lkA + 1][lmA] = a.y;
        As[lkA + 2][lmA] = a.z; As[lkA + 3][lmA] = a.w;
        *(float4*)&Bs[lkB][lnB] = *(const float4*)&Bt[(k0 + lkB) * Nc + n0 + lnB];
        __syncthreads();
        #pragma unroll
        for (int k = 0; k < 16; k++) {
            float4 av = *(const float4*)&As[k][trow << 2];
            float4 bv = *(const float4*)&Bs[k][tcol << 2];
            float ar[4] = {av.x, av.y, av.z, av.w};
            float br[4] = {bv.x, bv.y, bv.z, bv.w};
            #pragma unroll
            for (int i = 0; i < 4; i++)
                #pragma unroll
                for (int j = 0; j < 4; j++)
                    acc[i][j] = fmaf(ar[i], br[j], acc[i][j]);
        }
        __syncthreads();
    }

    float4 bb = *(const float4*)&bias[n0 + (tcol << 2)];
    const float bbr[4] = {bb.x, bb.y, bb.z, bb.w};
    #pragma unroll
    for (int i = 0; i < 4; i++) {
        const int m = m0 + (trow << 2) + i;
        float4 r;
        float v0 = acc[i][0] + bbr[0], v1 = acc[i][1] + bbr[1];
        float v2 = acc[i][2] + bbr[2], v3 = acc[i][3] + bbr[3];
        if (act) { v0 = lrelu(v0); v1 = lrelu(v1); v2 = lrelu(v2); v3 = lrelu(v3); }
        r.x = v0; r.y = v1; r.z = v2; r.w = v3;
        *(float4*)&C[m * Nc + n0 + (tcol << 2)] = r;
    }
}

// ---------------- final: softmax weights, weighted max-pool, concat, GEMV ----------------
__global__ void __launch_bounds__(256) final_kernel(const float* __restrict__ img,
                                                    const float* __restrict__ fb,
                                                    float* __restrict__ out)
{
    __shared__ float swgt[8][KNN];
    __shared__ int   sidx[8][KNN];
    __shared__ float sfin[8][416];
    const int w = threadIdx.x >> 5, lane = threadIdx.x & 31;
    const int n = blockIdx.x * 8 + w;

    const float4 pq = d_pts4[n];
    float negd = -INFINITY; int myi = 0;
    if (lane < KNN) {
        myi = d_knn[n * KNN + lane];
        float4 pc = d_pts4[myi];
        float dx = pq.x - pc.x, dy = pq.y - pc.y, dz = pq.z - pc.z;
        negd = -sqrtf(fmaxf(dx * dx + dy * dy + dz * dz, 1e-12f));
    }
    float m = negd;
    #pragma unroll
    for (int s = 16; s > 0; s >>= 1) m = fmaxf(m, __shfl_xor_sync(0xffffffffu, m, s));
    float e = (lane < KNN) ? expf(negd - m) : 0.f;
    float ss = e;
    #pragma unroll
    for (int s = 16; s > 0; s >>= 1) ss += __shfl_xor_sync(0xffffffffu, ss, s);
    if (lane < KNN) { swgt[w][lane] = e / ss; sidx[w][lane] = myi; }
    __syncwarp();

    float4 sf = make_float4(-INFINITY, -INFINITY, -INFINITY, -INFINITY);
    float4 sp = make_float4(-INFINITY, -INFINITY, -INFINITY, -INFINITY);
    #pragma unroll
    for (int k = 0; k < KNN; k++) {
        const int ik = sidx[w][k];
        const float wk = swgt[w][k];
        const float4 gv = *(const float4*)&d_g[ik * 128 + (lane << 2)];
        const float4 hv = *(const float4*)&d_h[ik * 128 + (lane << 2)];
        sf.x = fmaxf(sf.x, gv.x * wk); sf.y = fmaxf(sf.y, gv.y * wk);
        sf.z = fmaxf(sf.z, gv.z * wk); sf.w = fmaxf(sf.w, gv.w * wk);
        sp.x = fmaxf(sp.x, hv.x * wk); sp.y = fmaxf(sp.y, hv.y * wk);
        sp.z = fmaxf(sp.z, hv.z * wk); sp.w = fmaxf(sp.w, hv.w * wk);
    }
    const int c4 = lane << 2;
    sfin[w][c4 + 0] = lrelu(sp.x); sfin[w][c4 + 1] = lrelu(sp.y);
    sfin[w][c4 + 2] = lrelu(sp.z); sfin[w][c4 + 3] = lrelu(sp.w);
    sfin[w][128 + lane] = lrelu(img[lane * NPTS + n]);
    sfin[w][160 + c4 + 0] = lrelu(sf.x); sfin[w][160 + c4 + 1] = lrelu(sf.y);
    sfin[w][160 + c4 + 2] = lrelu(sf.z); sfin[w][160 + c4 + 3] = lrelu(sf.w);
    const float4 cv = *(const float4*)&d_cf[n * 128 + c4];
    sfin[w][288 + c4 + 0] = lrelu(cv.x); sfin[w][288 + c4 + 1] = lrelu(cv.y);
    sfin[w][288 + c4 + 2] = lrelu(cv.z); sfin[w][288 + c4 + 3] = lrelu(cv.w);
    __syncwarp();

    float acc = fb[lane];
    #pragma unroll 8
    for (int c = 0; c < 416; c++)
        acc = fmaf(sfin[w][c], d_T7[c * 32 + lane], acc);
    out[lane * NPTS + n] = acc;
}

// ---------------- launch ----------------
extern "C" void kernel_launch(void* const* d_in, const int* in_sizes, int n_in,
                              void* d_out, int out_size)
{
    const float* img   = (const float*)d_in[0];
    const float* cloud = (const float*)d_in[1];
    const float* c1w  = (const float*)d_in[2];  const float* c1b  = (const float*)d_in[3];
    const float* c2w  = (const float*)d_in[4];  const float* c2b  = (const float*)d_in[5];
    const float* ps1w = (const float*)d_in[6];  const float* ps1b = (const float*)d_in[7];
    const float* ps2w = (const float*)d_in[8];  const float* ps2b = (const float*)d_in[9];
    const float* pc1w = (const float*)d_in[10]; const float* pc1b = (const float*)d_in[11];
    const float* pc2w = (const float*)d_in[12]; const float* pc2b = (const float*)d_in[13];
    const float* finw = (const float*)d_in[14]; const float* finb = (const float*)d_in[15];
    float* out = (float*)d_out;

    void *pPtsPad, *pT1, *pT2, *pT3, *pT4, *pT5, *pT6;
    void *pt1, *pcf, *pimfT, *pt2, *pg, *ph1, *ph;
    cudaGetSymbolAddress(&pPtsPad, d_ptsPad);
    cudaGetSymbolAddress(&pT1, d_T1); cudaGetSymbolAddress(&pT2, d_T2);
    cudaGetSymbolAddress(&pT3, d_T3); cudaGetSymbolAddress(&pT4, d_T4);
    cudaGetSymbolAddress(&pT5, d_T5); cudaGetSymbolAddress(&pT6, d_T6);
    cudaGetSymbolAddress(&pt1, d_t1); cudaGetSymbolAddress(&pcf, d_cf);
    cudaGetSymbolAddress(&pimfT, d_imfT); cudaGetSymbolAddress(&pt2, d_t2);
    cudaGetSymbolAddress(&pg, d_g); cudaGetSymbolAddress(&ph1, d_h1);
    cudaGetSymbolAddress(&ph, d_h);

    prep_kernel<<<256, 256>>>(img, cloud, c1w, c2w, ps1w, ps2w, pc1w, pc2w, finw);
    hist_kernel<<<NPTS / 256, 256>>>(cloud);
    scan_kernel<<<1, 512>>>();
    scatter_kernel<<<NPTS / 256, 256>>>();

    // warp-per-query KNN: 16384 warps = 2048 blocks
    knn_warp_kernel<<<NPTS * 32 / 256, 256>>>();

    gemm_kernel<<<dim3(1, NPTS / 64), 256>>>((const float*)pPtsPad, (const float*)pT1, pc1b, (float*)pt1, 16, 64, 1);
    gemm_kernel<<<dim3(2, NPTS / 64), 256>>>((const float*)pt1, (const float*)pT2, pc2b, (float*)pcf, 64, 128, 0);
    gemm_kernel<<<dim3(1, NPTS / 64), 256>>>((const float*)pimfT, (const float*)pT3, c1b, (float*)pt2, 32, 64, 1);
    gemm_kernel<<<dim3(2, NPTS / 64), 256>>>((const float*)pt2, (const float*)pT4, c2b, (float*)pg, 64, 128, 0);
    gemm_kernel<<<dim3(4, NPTS / 64), 256>>>((const float*)pcf, (const float*)pT5, ps1b, (float*)ph1, 128, 256, 1);
    gemm_kernel<<<dim3(2, NPTS / 64), 256>>>((const float*)ph1, (const float*)pT6, ps2b, (float*)ph, 256, 128, 0);

    final_kernel<<<NPTS / 8, 256>>>(img, finb, out);
}

// round 8
// speedup vs baseline: 1.6422x; 1.1136x over previous
#include <cuda_runtime.h>
#include <cuda_bf16.h>
#include <math.h>

#define NPTS 16384
#define KNN  16
#define G    12
#define GC   (G * G * G)     // 1728 cells, ~9.5 pts/cell
#define HCELL (1.0f / G)
#define FULLM 0xffffffffu

// ---------------- scratch (device globals, no allocations) ----------------
__device__ float4 d_pts4[NPTS];
__device__ float  d_ptsPad[NPTS * 16];
__device__ float  d_imfT[NPTS * 32];
__device__ float  d_T1[16 * 64];
__device__ float  d_T2[64 * 128];
__device__ float  d_T3[32 * 64];
__device__ float  d_T4[64 * 128];
__device__ float  d_T5[128 * 256];
__device__ float  d_T6[256 * 128];
__device__ float  d_T7[416 * 32];
__device__ float  d_t1[NPTS * 64];
__device__ float  d_cf[NPTS * 128];
__device__ float  d_t2[NPTS * 64];
__device__ float  d_g [NPTS * 128];
__device__ float  d_h1[NPTS * 256];
__device__ float  d_h [NPTS * 128];
__device__ int    d_knn[NPTS * KNN];
// grid: [0:GC)=counts, [GC:2GC)=scatter cursors. Zero at module load; final_kernel
// re-zeroes them every invocation, so they are always zero on entry.
__device__ int    d_cellCnt[2 * GC];
__device__ int    d_cellStart[GC + 1];
__device__ int    d_ptCell[NPTS];
__device__ float4 d_spts[NPTS];
__device__ int    d_sidx[NPTS];

__device__ __forceinline__ float lrelu(float x) { return x > 0.f ? x : 0.01f * x; }

// ---------------- prep (+ fused hist; counters are pre-zeroed invariant) ----------------
__global__ void prep_kernel(const float* __restrict__ img, const float* __restrict__ cloud,
                            const float* __restrict__ c1w, const float* __restrict__ c2w,
                            const float* __restrict__ ps1w, const float* __restrict__ ps2w,
                            const float* __restrict__ pc1w, const float* __restrict__ pc2w,
                            const float* __restrict__ finw)
{
    const int stride = gridDim.x * blockDim.x;
    const int i0 = blockIdx.x * blockDim.x + threadIdx.x;
    for (int n = i0; n < NPTS; n += stride) {
        float x = cloud[n * 3 + 0], y = cloud[n * 3 + 1], z = cloud[n * 3 + 2];
        d_pts4[n] = make_float4(x, y, z, x * x + y * y + z * z);
        float* row = &d_ptsPad[n * 16];
        row[0] = x; row[1] = y; row[2] = z;
        #pragma unroll
        for (int k = 3; k < 16; k++) row[k] = 0.f;
        int cx = min(G - 1, max(0, (int)(x * G)));
        int cy = min(G - 1, max(0, (int)(y * G)));
        int cz = min(G - 1, max(0, (int)(z * G)));
        int c = (cz * G + cy) * G + cx;
        d_ptCell[n] = c;
        atomicAdd(&d_cellCnt[c], 1);
    }
    for (int t = i0; t < NPTS * 32; t += stride)
        d_imfT[t] = img[(t & 31) * NPTS + (t >> 5)];
    for (int t = i0; t < 16 * 64; t += stride) {
        int k = t >> 6, j = t & 63;
        d_T1[t] = (k < 3) ? pc1w[j * 3 + k] : 0.f;
    }
    for (int t = i0; t < 64 * 128; t += stride) { int k = t >> 7, c = t & 127; d_T2[t] = pc2w[c * 64 + k]; }
    for (int t = i0; t < 32 * 64;  t += stride) { int k = t >> 6, j = t & 63;  d_T3[t] = c1w[j * 32 + k]; }
    for (int t = i0; t < 64 * 128; t += stride) { int k = t >> 7, c = t & 127; d_T4[t] = c2w[c * 64 + k]; }
    for (int t = i0; t < 128 * 256; t += stride) { int k = t >> 8, c = t & 255; d_T5[t] = ps1w[c * 128 + k]; }
    for (int t = i0; t < 256 * 128; t += stride) { int k = t >> 7, c = t & 127; d_T6[t] = ps2w[c * 256 + k]; }
    for (int t = i0; t < 416 * 32;  t += stride) { int c = t >> 5, j = t & 31;  d_T7[t] = finw[j * 416 + c]; }
}

// ---------------- grid build ----------------
__global__ void scan_kernel()   // one block, 512 threads, 1728 cells
{
    __shared__ int ssum[512];
    const int t = threadIdx.x;
    int c0 = 0, c1 = 0, c2 = 0, c3 = 0;
    if (4 * t < GC) {
        c0 = d_cellCnt[4 * t + 0]; c1 = d_cellCnt[4 * t + 1];
        c2 = d_cellCnt[4 * t + 2]; c3 = d_cellCnt[4 * t + 3];
    }
    int s = c0 + c1 + c2 + c3;
    ssum[t] = s;
    __syncthreads();
    for (int off = 1; off < 512; off <<= 1) {
        int v = (t >= off) ? ssum[t - off] : 0;
        __syncthreads();
        ssum[t] += v;
        __syncthreads();
    }
    int excl = ssum[t] - s;
    if (4 * t < GC) {
        d_cellStart[4 * t + 0] = excl;
        d_cellStart[4 * t + 1] = excl + c0;
        d_cellStart[4 * t + 2] = excl + c0 + c1;
        d_cellStart[4 * t + 3] = excl + c0 + c1 + c2;
    }
    if (t == 511) d_cellStart[GC] = ssum[511];
}

__global__ void scatter_kernel()
{
    const int n = blockIdx.x * blockDim.x + threadIdx.x;
    if (n >= NPTS) return;
    const int c = d_ptCell[n];
    const int pos = d_cellStart[c] + atomicAdd(&d_cellCnt[GC + c], 1);
    d_spts[pos] = d_pts4[n];
    d_sidx[pos] = n;
}

// ---------------- KNN: one WARP per query, distributed top-16 ----------------
__device__ __forceinline__ void warp_scan_range(int st, int en, int lane,
                                                float qx, float qy, float qz,
                                                float& e, int& ei, float& thresh)
{
    const int nb = (en - st + 31) >> 5;
    for (int b = 0; b < nb; b++) {
        const int p = st + (b << 5) + lane;
        float dcand = INFINITY;
        if (p < en) {
            const float4 c = d_spts[p];
            const float dx = qx - c.x, dy = qy - c.y, dz = qz - c.z;
            dcand = fmaf(dx, dx, fmaf(dy, dy, dz * dz));
        }
        unsigned mask = __ballot_sync(FULLM, dcand <= thresh);
        while (mask) {
            const int src = __ffs(mask) - 1;
            mask &= mask - 1;
            const float v = __shfl_sync(FULLM, dcand, src);
            const int  vi = __shfl_sync(FULLM, p,     src);
            if (v <= thresh) {              // uniform
                const unsigned le = __ballot_sync(FULLM, e <= v) & 0xFFFFu;
                const int pos = __popc(le);
                const float pe = __shfl_up_sync(FULLM, e, 1);
                const int  pei = __shfl_up_sync(FULLM, ei, 1);
                if (lane > pos) { e = pe; ei = pei; }
                if (lane == pos) { e = v; ei = vi; }
                thresh = fminf(thresh, __shfl_sync(FULLM, e, 15));
            }
        }
    }
}

__global__ void __launch_bounds__(256) knn_warp_kernel()
{
    const int lane = threadIdx.x & 31;
    const int s = (blockIdx.x * 256 + threadIdx.x) >> 5;   // query = sorted position
    const float4 pq = d_spts[s];
    const int cx = min(G - 1, max(0, (int)(pq.x * G)));
    const int cy = min(G - 1, max(0, (int)(pq.y * G)));
    const int cz = min(G - 1, max(0, (int)(pq.z * G)));

    float e = INFINITY; int ei = 0;
    // --- seed thresh: provable upper bound on 16th-NN distance from 32
    // sorted-order neighbors (spatially coherent). bound = max over 4 groups
    // of 8 of each group's 4th-smallest >= 16th-smallest of 32 >= true kd15.
    float thresh;
    {
        const int base = min(max(s - 15, 0), NPTS - 32);
        const float4 c = d_spts[base + lane];
        const float dx = pq.x - c.x, dy = pq.y - c.y, dz = pq.z - c.z;
        float v = fmaf(dx, dx, fmaf(dy, dy, dz * dz));
        const int local = lane & 7;
        // bitonic sort each 8-lane group ascending (local index)
        {
            float o; bool lower, asc;
            o = __shfl_xor_sync(FULLM, v, 1); lower = !(local & 1); asc = !(local & 2);
            v = (lower == asc) ? fminf(v, o) : fmaxf(v, o);
            o = __shfl_xor_sync(FULLM, v, 2); lower = !(local & 2); asc = !(local & 4);
            v = (lower == asc) ? fminf(v, o) : fmaxf(v, o);
            o = __shfl_xor_sync(FULLM, v, 1); lower = !(local & 1); asc = !(local & 4);
            v = (lower == asc) ? fminf(v, o) : fmaxf(v, o);
            o = __shfl_xor_sync(FULLM, v, 4); lower = !(local & 4);
            v = lower ? fminf(v, o) : fmaxf(v, o);
            o = __shfl_xor_sync(FULLM, v, 2); lower = !(local & 2);
            v = lower ? fminf(v, o) : fmaxf(v, o);
            o = __shfl_xor_sync(FULLM, v, 1); lower = !(local & 1);
            v = lower ? fminf(v, o) : fmaxf(v, o);
        }
        float m3 = __shfl_sync(FULLM, v, (lane & ~7) + 3);   // group's 4th smallest
        m3 = fmaxf(m3, __shfl_xor_sync(FULLM, m3, 8));
        m3 = fmaxf(m3, __shfl_xor_sync(FULLM, m3, 16));
        thresh = m3;
    }

    for (int m = 0; m < G; m++) {
        const int x0 = max(cx - m, 0), x1 = min(cx + m, G - 1);
        const int y0 = max(cy - m, 0), y1 = min(cy + m, G - 1);
        const int z0 = max(cz - m, 0), z1 = min(cz + m, G - 1);
        for (int z = z0; z <= z1; z++) {
            const bool zs = (z == cz - m) || (z == cz + m);
            for (int y = y0; y <= y1; y++) {
                const bool edge = zs || (y == cy - m) || (y == cy + m);
                const int rowc = (z * G + y) * G;
                if (edge) {
                    warp_scan_range(d_cellStart[rowc + x0], d_cellStart[rowc + x1 + 1],
                                    lane, pq.x, pq.y, pq.z, e, ei, thresh);
                } else {
                    if (cx - m >= 0)
                        warp_scan_range(d_cellStart[rowc + cx - m], d_cellStart[rowc + cx - m + 1],
                                        lane, pq.x, pq.y, pq.z, e, ei, thresh);
                    if (cx + m <= G - 1)
                        warp_scan_range(d_cellStart[rowc + cx + m], d_cellStart[rowc + cx + m + 1],
                                        lane, pq.x, pq.y, pq.z, e, ei, thresh);
                }
            }
        }
        const float bound = (float)m * HCELL;
        // e15 >= true kd15 always; stop only when list's 16th is certain
        const float e15 = __shfl_sync(FULLM, e, 15);
        if (e15 < bound * bound) break;
    }

    if (lane < KNN) {
        const int orig = d_sidx[s];
        d_knn[orig * KNN + lane] = d_sidx[ei];
    }
}

// ---------------- generic fp32 GEMM ----------------
__global__ void __launch_bounds__(256) gemm_kernel(const float* __restrict__ A,
                                                   const float* __restrict__ Bt,
                                                   const float* __restrict__ bias,
                                                   float* __restrict__ C,
                                                   int K, int Nc, int act)
{
    __shared__ float As[16][68];
    __shared__ float Bs[16][64];
    const int tid  = threadIdx.x;
    const int tcol = tid & 15, trow = tid >> 4;
    const int m0 = blockIdx.y * 64, n0 = blockIdx.x * 64;
    const int lmA = tid >> 2, lkA = (tid & 3) << 2;
    const int lkB = tid >> 4, lnB = (tid & 15) << 2;

    float acc[4][4];
    #pragma unroll
    for (int i = 0; i < 4; i++)
        #pragma unroll
        for (int j = 0; j < 4; j++) acc[i][j] = 0.f;

    for (int k0 = 0; k0 < K; k0 += 16) {
        float4 a = *(const float4*)&A[(m0 + lmA) * K + k0 + lkA];
        As[lkA + 0][lmA] = a.x; As[lkA + 1][lmA] = a.y;
        As[lkA + 2][lmA] = a.z; As[lkA + 3][lmA] = a.w;
        *(float4*)&Bs[lkB][lnB] = *(const float4*)&Bt[(k0 + lkB) * Nc + n0 + lnB];
        __syncthreads();
        #pragma unroll
        for (int k = 0; k < 16; k++) {
            float4 av = *(const float4*)&As[k][trow << 2];
            float4 bv = *(const float4*)&Bs[k][tcol << 2];
            float ar[4] = {av.x, av.y, av.z, av.w};
            float br[4] = {bv.x, bv.y, bv.z, bv.w};
            #pragma unroll
            for (int i = 0; i < 4; i++)
                #pragma unroll
                for (int j = 0; j < 4; j++)
                    acc[i][j] = fmaf(ar[i], br[j], acc[i][j]);
        }
        __syncthreads();
    }

    float4 bb = *(const float4*)&bias[n0 + (tcol << 2)];
    const float bbr[4] = {bb.x, bb.y, bb.z, bb.w};
    #pragma unroll
    for (int i = 0; i < 4; i++) {
        const int m = m0 + (trow << 2) + i;
        float4 r;
        float v0 = acc[i][0] + bbr[0], v1 = acc[i][1] + bbr[1];
        float v2 = acc[i][2] + bbr[2], v3 = acc[i][3] + bbr[3];
        if (act) { v0 = lrelu(v0); v1 = lrelu(v1); v2 = lrelu(v2); v3 = lrelu(v3); }
        r.x = v0; r.y = v1; r.z = v2; r.w = v3;
        *(float4*)&C[m * Nc + n0 + (tcol << 2)] = r;
    }
}

// ---------------- final (+ re-zero grid counters for next invocation) ----------------
__global__ void __launch_bounds__(256) final_kernel(const float* __restrict__ img,
                                                    const float* __restrict__ fb,
                                                    float* __restrict__ out)
{
    __shared__ float swgt[8][KNN];
    __shared__ int   sidx[8][KNN];
    __shared__ float sfin[8][416];
    const int w = threadIdx.x >> 5, lane = threadIdx.x & 31;
    const int n = blockIdx.x * 8 + w;

    // restore counter invariant (2*GC ints across grid)
    for (int t = blockIdx.x * blockDim.x + threadIdx.x; t < 2 * GC; t += gridDim.x * blockDim.x)
        d_cellCnt[t] = 0;

    const float4 pq = d_pts4[n];
    float negd = -INFINITY; int myi = 0;
    if (lane < KNN) {
        myi = d_knn[n * KNN + lane];
        float4 pc = d_pts4[myi];
        float dx = pq.x - pc.x, dy = pq.y - pc.y, dz = pq.z - pc.z;
        negd = -sqrtf(fmaxf(dx * dx + dy * dy + dz * dz, 1e-12f));
    }
    float m = negd;
    #pragma unroll
    for (int s = 16; s > 0; s >>= 1) m = fmaxf(m, __shfl_xor_sync(0xffffffffu, m, s));
    float e = (lane < KNN) ? expf(negd - m) : 0.f;
    float ss = e;
    #pragma unroll
    for (int s = 16; s > 0; s >>= 1) ss += __shfl_xor_sync(0xffffffffu, ss, s);
    if (lane < KNN) { swgt[w][lane] = e / ss; sidx[w][lane] = myi; }
    __syncwarp();

    float4 sf = make_float4(-INFINITY, -INFINITY, -INFINITY, -INFINITY);
    float4 sp = make_float4(-INFINITY, -INFINITY, -INFINITY, -INFINITY);
    #pragma unroll
    for (int k = 0; k < KNN; k++) {
        const int ik = sidx[w][k];
        const float wk = swgt[w][k];
        const float4 gv = *(const float4*)&d_g[ik * 128 + (lane << 2)];
        const float4 hv = *(const float4*)&d_h[ik * 128 + (lane << 2)];
        sf.x = fmaxf(sf.x, gv.x * wk); sf.y = fmaxf(sf.y, gv.y * wk);
        sf.z = fmaxf(sf.z, gv.z * wk); sf.w = fmaxf(sf.w, gv.w * wk);
        sp.x = fmaxf(sp.x, hv.x * wk); sp.y = fmaxf(sp.y, hv.y * wk);
        sp.z = fmaxf(sp.z, hv.z * wk); sp.w = fmaxf(sp.w, hv.w * wk);
    }
    const int c4 = lane << 2;
    sfin[w][c4 + 0] = lrelu(sp.x); sfin[w][c4 + 1] = lrelu(sp.y);
    sfin[w][c4 + 2] = lrelu(sp.z); sfin[w][c4 + 3] = lrelu(sp.w);
    sfin[w][128 + lane] = lrelu(img[lane * NPTS + n]);
    sfin[w][160 + c4 + 0] = lrelu(sf.x); sfin[w][160 + c4 + 1] = lrelu(sf.y);
    sfin[w][160 + c4 + 2] = lrelu(sf.z); sfin[w][160 + c4 + 3] = lrelu(sf.w);
    const float4 cv = *(const float4*)&d_cf[n * 128 + c4];
    sfin[w][288 + c4 + 0] = lrelu(cv.x); sfin[w][288 + c4 + 1] = lrelu(cv.y);
    sfin[w][288 + c4 + 2] = lrelu(cv.z); sfin[w][288 + c4 + 3] = lrelu(cv.w);
    __syncwarp();

    float acc = fb[lane];
    #pragma unroll 8
    for (int c = 0; c < 416; c++)
        acc = fmaf(sfin[w][c], d_T7[c * 32 + lane], acc);
    out[lane * NPTS + n] = acc;
}

// ---------------- launch ----------------
extern "C" void kernel_launch(void* const* d_in, const int* in_sizes, int n_in,
                              void* d_out, int out_size)
{
    const float* img   = (const float*)d_in[0];
    const float* cloud = (const float*)d_in[1];
    const float* c1w  = (const float*)d_in[2];  const float* c1b  = (const float*)d_in[3];
    const float* c2w  = (const float*)d_in[4];  const float* c2b  = (const float*)d_in[5];
    const float* ps1w = (const float*)d_in[6];  const float* ps1b = (const float*)d_in[7];
    const float* ps2w = (const float*)d_in[8];  const float* ps2b = (const float*)d_in[9];
    const float* pc1w = (const float*)d_in[10]; const float* pc1b = (const float*)d_in[11];
    const float* pc2w = (const float*)d_in[12]; const float* pc2b = (const float*)d_in[13];
    const float* finw = (const float*)d_in[14]; const float* finb = (const float*)d_in[15];
    float* out = (float*)d_out;

    void *pPtsPad, *pT1, *pT2, *pT3, *pT4, *pT5, *pT6;
    void *pt1, *pcf, *pimfT, *pt2, *pg, *ph1, *ph;
    cudaGetSymbolAddress(&pPtsPad, d_ptsPad);
    cudaGetSymbolAddress(&pT1, d_T1); cudaGetSymbolAddress(&pT2, d_T2);
    cudaGetSymbolAddress(&pT3, d_T3); cudaGetSymbolAddress(&pT4, d_T4);
    cudaGetSymbolAddress(&pT5, d_T5); cudaGetSymbolAddress(&pT6, d_T6);
    cudaGetSymbolAddress(&pt1, d_t1); cudaGetSymbolAddress(&pcf, d_cf);
    cudaGetSymbolAddress(&pimfT, d_imfT); cudaGetSymbolAddress(&pt2, d_t2);
    cudaGetSymbolAddress(&pg, d_g); cudaGetSymbolAddress(&ph1, d_h1);
    cudaGetSymbolAddress(&ph, d_h);

    static cudaStream_t s1 = nullptr;
    static cudaEvent_t evFork = nullptr, evJoin = nullptr;
    if (s1 == nullptr) {
        cudaStreamCreateWithFlags(&s1, cudaStreamNonBlocking);
        cudaEventCreateWithFlags(&evFork, cudaEventDisableTiming);
        cudaEventCreateWithFlags(&evJoin, cudaEventDisableTiming);
    }

    // main stream: prep -> scan -> scatter -> knn   (knn = my 4th kernel)
    prep_kernel<<<256, 256>>>(img, cloud, c1w, c2w, ps1w, ps2w, pc1w, pc2w, finw);
    cudaEventRecord(evFork, 0);
    scan_kernel<<<1, 512>>>();
    scatter_kernel<<<NPTS / 256, 256>>>();
    knn_warp_kernel<<<NPTS * 32 / 256, 256>>>();

    // side stream: GEMM chain overlaps scan/scatter/knn (depends only on prep)
    cudaStreamWaitEvent(s1, evFork, 0);
    gemm_kernel<<<dim3(1, NPTS / 64), 256, 0, s1>>>((const float*)pPtsPad, (const float*)pT1, pc1b, (float*)pt1, 16, 64, 1);
    gemm_kernel<<<dim3(2, NPTS / 64), 256, 0, s1>>>((const float*)pt1, (const float*)pT2, pc2b, (float*)pcf, 64, 128, 0);
    gemm_kernel<<<dim3(1, NPTS / 64), 256, 0, s1>>>((const float*)pimfT, (const float*)pT3, c1b, (float*)pt2, 32, 64, 1);
    gemm_kernel<<<dim3(2, NPTS / 64), 256, 0, s1>>>((const float*)pt2, (const float*)pT4, c2b, (float*)pg, 64, 128, 0);
    gemm_kernel<<<dim3(4, NPTS / 64), 256, 0, s1>>>((const float*)pcf, (const float*)pT5, ps1b, (float*)ph1, 128, 256, 1);
    gemm_kernel<<<dim3(2, NPTS / 64), 256, 0, s1>>>((const float*)ph1, (const float*)pT6, ps2b, (float*)ph, 256, 128, 0);
    cudaEventRecord(evJoin, s1);

    // join, then final
    cudaStreamWaitEvent(0, evJoin, 0);
    final_kernel<<<NPTS / 8, 256>>>(img, finb, out);
}